// round 7
// baseline (speedup 1.0000x reference)
#include <cuda_runtime.h>
#include <math.h>
#include <stdint.h>

// ---------------------------------------------------------------------------
// Problem constants
// ---------------------------------------------------------------------------
#define B_ 8
#define T_ 4096
#define D_ 512
#define M_TOTAL (B_ * T_)          // 32768
#define CHUNK 128
#define NCHUNK (T_ / CHUNK)        // 32
#define NST 16                     // k-stages (BK=32)

// ---------------------------------------------------------------------------
// Scratch
// ---------------------------------------------------------------------------
__device__ float g_bufA[(size_t)M_TOTAL * D_];   // interleaved
__device__ float g_bufB[(size_t)M_TOTAL * D_];
__device__ float g_partial[B_ * NCHUNK * D_];
__device__ float g_summ[B_ * D_];
__device__ float g_Wt[3 * (size_t)D_ * D_];      // transposed+interleaved tf32

// ---------------------------------------------------------------------------
// Helpers
// ---------------------------------------------------------------------------
__device__ __forceinline__ uint32_t smem_u32(const void* p) {
    uint32_t a;
    asm("{ .reg .u64 t; cvta.to.shared.u64 t, %1; cvt.u32.u64 %0, t; }"
        : "=r"(a) : "l"(p));
    return a;
}
__device__ __forceinline__ float to_tf32(float x) {
    uint32_t u; asm("cvt.rna.tf32.f32 %0, %1;" : "=r"(u) : "f"(x));
    return __uint_as_float(u);
}
__device__ __forceinline__ void mma_tf32_16x8x8(float* d, const uint32_t* a,
                                                const uint32_t* b) {
    asm volatile(
        "mma.sync.aligned.m16n8k8.row.col.f32.tf32.tf32.f32 "
        "{%0,%1,%2,%3}, {%4,%5,%6,%7}, {%8,%9}, {%0,%1,%2,%3};"
        : "+f"(d[0]), "+f"(d[1]), "+f"(d[2]), "+f"(d[3])
        : "r"(a[0]), "r"(a[1]), "r"(a[2]), "r"(a[3]),
          "r"(b[0]), "r"(b[1]));
}

#define CP_ASYNC16(dst, src) \
    asm volatile("cp.async.cg.shared.global [%0], [%1], 16;" \
                 :: "r"(dst), "l"(src) : "memory")
#define CP_COMMIT() asm volatile("cp.async.commit_group;" ::: "memory")
#define CP_WAIT1()  asm volatile("cp.async.wait_group 1;" ::: "memory")
#define CP_WAIT0()  asm volatile("cp.async.wait_group 0;" ::: "memory")

// Interleave v2 (GMEM): within a 32-wide k-stage, kk -> col so that
// (k, k+4, k+8, k+12) are contiguous (one LDS.128 = 2 k-groups).
__device__ __forceinline__ int kcol32(int kk) {
    return ((kk >> 4) << 4) + ((kk & 3) << 2) + ((kk & 15) >> 2);
}
__device__ __forceinline__ size_t ileave(int m, int k) {
    return ((size_t)((m >> 7) * NST + (k >> 5)) * 128 + (m & 127)) * 32
           + kcol32(k & 31);
}
// SMEM XOR swizzle of 16B chunks: chunk' = chunk ^ swz8(row)
__device__ __forceinline__ int swz8(int r) {
    return (((r & 1) << 2) | ((r >> 1) & 3));
}

// ---------------------------------------------------------------------------
// chunk_sum (launch 0)
// ---------------------------------------------------------------------------
__global__ void chunk_sum_kernel(const float* __restrict__ dec) {
    int bc = blockIdx.x;
    int b = bc / NCHUNK, c = bc % NCHUNK;
    int d = threadIdx.x;
    const float* p = dec + ((size_t)(b * T_ + c * CHUNK)) * D_ + d;
    float s = 0.f;
    #pragma unroll 8
    for (int t = 0; t < CHUNK; ++t) s += p[(size_t)t * D_];
    g_partial[(size_t)bc * D_ + d] = s;
}

// ---------------------------------------------------------------------------
// prep_kernel (launch 1): chunk_prefix + 3 weight transposes + summ_proj
// ---------------------------------------------------------------------------
__global__ __launch_bounds__(512)
void prep_kernel(const float* __restrict__ summ, const float* __restrict__ W1,
                 const float* __restrict__ W_hist, const float* __restrict__ W2,
                 const float* __restrict__ W_out) {
    __shared__ float sh[1056];
    int blk = blockIdx.x;
    int tid = threadIdx.x;

    if (blk < 8) {                         // ---- chunk exclusive prefix ----
        int b = blk, d = tid;
        float run = 0.f;
        for (int c = 0; c < NCHUNK; ++c) {
            size_t idx = ((size_t)(b * NCHUNK + c)) * D_ + d;
            float v = g_partial[idx];
            g_partial[idx] = run;
            run += v;
        }
    } else if (blk < 8 + 768) {            // ---- weight transpose+interleave ----
        int idx = blk - 8;
        int w = idx >> 8;
        int r = idx & 255;
        const float* W = (w == 0) ? W_hist : (w == 1) ? W2 : W_out;
        float* Wt = g_Wt + (size_t)w * D_ * D_;
        int bx = (r & 15) * 32, by = (r >> 4) * 32;
        if (tid < 256) {
            int x = tid & 31, y = tid >> 5;
            float(*t)[33] = (float(*)[33])sh;
            #pragma unroll
            for (int i = 0; i < 32; i += 8)
                t[y + i][x] = W[(size_t)(by + y + i) * D_ + bx + x];
            __syncthreads();
            #pragma unroll
            for (int i = 0; i < 32; i += 8)
                Wt[ileave(bx + y + i, by + x)] = to_tf32(t[x][y + i]);
        } else {
            __syncthreads();
        }
    } else {                               // ---- summ_proj ----
        int sidx = blk - 776;
        int b = sidx >> 2;
        int n0 = (sidx & 3) * 128;
        float* s = sh;
        float* red = sh + 512;
        int nl = tid & 127;
        int kg = tid >> 7;
        for (int i = tid; i < D_; i += 512) s[i] = summ[b * D_ + i];
        __syncthreads();
        float acc = 0.f;
        int k0 = kg * 128;
        #pragma unroll 8
        for (int k = 0; k < 128; ++k)
            acc = fmaf(s[k0 + k], W1[(size_t)(k0 + k) * D_ + n0 + nl], acc);
        red[kg * 128 + nl] = acc;
        __syncthreads();
        if (kg == 0)
            g_summ[b * D_ + n0 + nl] =
                red[nl] + red[128 + nl] + red[256 + nl] + red[384 + nl];
    }
}

// ---------------------------------------------------------------------------
// cum_mean (launch 2) -> g_bufA (tf32, interleaved v2), 4x unrolled for MLP
// ---------------------------------------------------------------------------
__global__ void cum_mean_kernel(const float* __restrict__ dec) {
    int bc = blockIdx.x;
    int b = bc / NCHUNK, c = bc % NCHUNK;
    int d = threadIdx.x;
    size_t base = ((size_t)(b * T_ + c * CHUNK)) * D_ + d;
    float run = g_partial[(size_t)bc * D_ + d];
    size_t obase = ((size_t)((b * NCHUNK + c) * NST + (d >> 5)) * 128) * 32
                   + kcol32(d & 31);
    for (int t = 0; t < CHUNK; t += 4) {
        float v0 = dec[base + (size_t)(t + 0) * D_];
        float v1 = dec[base + (size_t)(t + 1) * D_];
        float v2 = dec[base + (size_t)(t + 2) * D_];
        float v3 = dec[base + (size_t)(t + 3) * D_];
        int tt = c * CHUNK + t;
        run += v0;
        g_bufA[obase + (size_t)(t + 0) * 32] = to_tf32(run / (float)(tt + 1));
        run += v1;
        g_bufA[obase + (size_t)(t + 1) * 32] = to_tf32(run / (float)(tt + 2));
        run += v2;
        g_bufA[obase + (size_t)(t + 2) * 32] = to_tf32(run / (float)(tt + 3));
        run += v3;
        g_bufA[obase + (size_t)(t + 3) * 32] = to_tf32(run / (float)(tt + 4));
    }
}

// ---------------------------------------------------------------------------
// tc_gemm: mma.sync tf32, 3-stage cp.async ring, XOR-swizzled packed SMEM.
// Tile 128x64, 8 warps (4m x 2n), warp tile 32x32, 3 CTAs/SM.
//   MODE 0: C(il) = tf32(tanh(acc + bias[col]))
//   MODE 1: C(il) = tf32(summ_proj[b][col] - acc)
//   MODE 2: C plain = tanh(acc + bias[col]) + resid
// ---------------------------------------------------------------------------
#define GM_THREADS 256
#define TILE_M 128
#define TILE_N 64
#define STG_A 16384                        // 128 rows x 128B
#define STG_B 8192                         // 64 rows x 128B

#define SM_A   0
#define SM_B   (3 * STG_A)                 // 49152
#define GEMM_SMEM (SM_B + 3 * STG_B)       // 73728 = 72KB -> 3 CTAs/SM

template <int MODE>
__global__ __launch_bounds__(GM_THREADS, 3)
void tc_gemm(const float* __restrict__ A, const float* __restrict__ Bt,
             const float* __restrict__ vec, const float* __restrict__ resid,
             float* __restrict__ C) {
    extern __shared__ char smem[];
    const uint32_t sbase = smem_u32(smem);

    const int tid = threadIdx.x;
    const int wid = tid >> 5, lane = tid & 31;
    const int row0 = blockIdx.y * TILE_M;
    const int col0 = blockIdx.x * TILE_N;
    const int wm = (wid & 3) * 32;
    const int wn = (wid >> 2) * 32;        // 0 or 32 (local col base)
    const int lq = lane >> 2;              // 0..7
    const int lr = lane & 3;               // 0..3

    const char* Ab = (const char*)(A + (size_t)blockIdx.y * NST * 4096);
    const char* Bb = (const char*)Bt + (size_t)(col0 >> 7) * NST * 16384
                     + (size_t)(col0 & 127) * 128;
    const int frow = tid >> 3;             // 0..31
    const int fq = tid & 7;
    const uint32_t stchunk = (uint32_t)((fq ^ swz8(frow)) << 4);

    auto issue_stage = [&](int s, int buf) {
        const char* as = Ab + (size_t)s * 16384;
        const char* bs = Bb + (size_t)s * 16384;
        uint32_t da = sbase + SM_A + buf * STG_A + frow * 128 + stchunk;
        uint32_t db = sbase + SM_B + buf * STG_B + frow * 128 + stchunk;
        const char* sa = as + (size_t)frow * 128 + fq * 16;
        const char* sb = bs + (size_t)frow * 128 + fq * 16;
        #pragma unroll
        for (int i = 0; i < 4; ++i)
            CP_ASYNC16(da + i * 4096, sa + (size_t)i * 4096);
        #pragma unroll
        for (int i = 0; i < 2; ++i)
            CP_ASYNC16(db + i * 4096, sb + (size_t)i * 4096);
    };

    // per-thread fragment chunk offsets (floats) within a 128B row
    const int swzl = swz8(lq);
    const int co0 = (lr ^ swzl) << 2;          // h=0 chunk
    const int co1 = ((4 + lr) ^ swzl) << 2;    // h=1 chunk

    float acc[2][4][4];
    #pragma unroll
    for (int mt = 0; mt < 2; ++mt)
        #pragma unroll
        for (int nt = 0; nt < 4; ++nt)
            #pragma unroll
            for (int j = 0; j < 4; ++j) acc[mt][nt][j] = 0.f;

    issue_stage(0, 0); CP_COMMIT();
    issue_stage(1, 1); CP_COMMIT();

    int buf = 0;
    for (int s = 0; s < NST; ++s) {
        if (s == NST - 1) { CP_WAIT0(); } else { CP_WAIT1(); }
        __syncthreads();
        if (s + 2 < NST) {
            int bufn = buf + 2; if (bufn >= 3) bufn -= 3;
            issue_stage(s + 2, bufn);
            CP_COMMIT();
        }

        const float* sa = (const float*)(smem + SM_A + buf * STG_A);
        const float* sb = (const float*)(smem + SM_B + buf * STG_B);

        #pragma unroll
        for (int h = 0; h < 2; ++h) {
            const int co = h ? co1 : co0;
            float4 a4[2][2];
            #pragma unroll
            for (int mt = 0; mt < 2; ++mt) {
                int r = wm + mt * 16 + lq;
                a4[mt][0] = *(const float4*)&sa[r * 32 + co];
                a4[mt][1] = *(const float4*)&sa[(r + 8) * 32 + co];
            }
            uint32_t ae[2][4], ao[2][4];
            #pragma unroll
            for (int mt = 0; mt < 2; ++mt) {
                ae[mt][0] = __float_as_uint(a4[mt][0].x);
                ae[mt][1] = __float_as_uint(a4[mt][1].x);
                ae[mt][2] = __float_as_uint(a4[mt][0].y);
                ae[mt][3] = __float_as_uint(a4[mt][1].y);
                ao[mt][0] = __float_as_uint(a4[mt][0].z);
                ao[mt][1] = __float_as_uint(a4[mt][1].z);
                ao[mt][2] = __float_as_uint(a4[mt][0].w);
                ao[mt][3] = __float_as_uint(a4[mt][1].w);
            }
            #pragma unroll
            for (int nt = 0; nt < 4; ++nt) {
                int n = wn + nt * 8 + lq;
                float4 b4 = *(const float4*)&sb[n * 32 + co];
                uint32_t be[2] = { __float_as_uint(b4.x), __float_as_uint(b4.y) };
                uint32_t bo[2] = { __float_as_uint(b4.z), __float_as_uint(b4.w) };
                mma_tf32_16x8x8(acc[0][nt], ae[0], be);
                mma_tf32_16x8x8(acc[1][nt], ae[1], be);
                mma_tf32_16x8x8(acc[0][nt], ao[0], bo);
                mma_tf32_16x8x8(acc[1][nt], ao[1], bo);
            }
        }
        if (++buf == 3) buf = 0;
    }

    // ---------------- Epilogue (vec read via L1/L2, no smem) ----------------
    const float* vbase = (MODE == 1) ? (vec + (size_t)(row0 / T_) * D_ + col0)
                                     : (vec + col0);
    if (MODE == 2) {
        #pragma unroll
        for (int mt = 0; mt < 2; ++mt) {
            int row = row0 + wm + mt * 16 + lq;
            #pragma unroll
            for (int nt = 0; nt < 4; ++nt) {
                int col = wn + nt * 8 + lr * 2;
                float b0 = vbase[col], b1 = vbase[col + 1];
                float c0 = acc[mt][nt][0], c1 = acc[mt][nt][1];
                float c2 = acc[mt][nt][2], c3 = acc[mt][nt][3];
                const float* r0p = resid + (size_t)row * D_ + col0 + col;
                const float* r1p = resid + (size_t)(row + 8) * D_ + col0 + col;
                float2 o0, o1;
                o0.x = tanhf(c0 + b0) + r0p[0];
                o0.y = tanhf(c1 + b1) + r0p[1];
                o1.x = tanhf(c2 + b0) + r1p[0];
                o1.y = tanhf(c3 + b1) + r1p[1];
                *(float2*)(C + (size_t)row * D_ + col0 + col) = o0;
                *(float2*)(C + (size_t)(row + 8) * D_ + col0 + col) = o1;
            }
        }
    } else {
        const size_t tilebase = (size_t)blockIdx.y * NST * 4096;
        #pragma unroll
        for (int mt = 0; mt < 2; ++mt) {
            int r = wm + mt * 16 + lq;
            #pragma unroll
            for (int nt = 0; nt < 4; ++nt) {
                int col = wn + nt * 8 + lr * 2;
                int k = col0 + col;
                size_t off = tilebase + (size_t)(k >> 5) * 4096
                             + (size_t)r * 32 + kcol32(k & 31);
                float b0 = vbase[col], b1 = vbase[col + 1];
                float c0 = acc[mt][nt][0], c1 = acc[mt][nt][1];
                float c2 = acc[mt][nt][2], c3 = acc[mt][nt][3];
                float v0, v1, v2, v3;
                if (MODE == 0) {
                    v0 = to_tf32(tanhf(c0 + b0));
                    v1 = to_tf32(tanhf(c1 + b1));
                    v2 = to_tf32(tanhf(c2 + b0));
                    v3 = to_tf32(tanhf(c3 + b1));
                } else {
                    v0 = to_tf32(b0 - c0);
                    v1 = to_tf32(b1 - c1);
                    v2 = to_tf32(b0 - c2);
                    v3 = to_tf32(b1 - c3);
                }
                C[off]       = v0;    // (r,   k)
                C[off + 4]   = v1;    // (r,   k+1)
                C[off + 256] = v2;    // (r+8, k)
                C[off + 260] = v3;    // (r+8, k+1)
            }
        }
    }
}

// ---------------------------------------------------------------------------
// LayerNorm (launch 6)
// ---------------------------------------------------------------------------
__global__ __launch_bounds__(256)
void layernorm_kernel(const float* __restrict__ X,
                      const float* __restrict__ gamma,
                      const float* __restrict__ beta,
                      float* __restrict__ out) {
    int row = blockIdx.x;
    const float* x = X + (size_t)row * D_;
    int tid = threadIdx.x;

    float v0 = x[tid];
    float v1 = x[tid + 256];
    float s = v0 + v1;
    float sq = v0 * v0 + v1 * v1;

    __shared__ float redS[8], redQ[8];
    #pragma unroll
    for (int o = 16; o > 0; o >>= 1) {
        s  += __shfl_down_sync(0xffffffffu, s, o);
        sq += __shfl_down_sync(0xffffffffu, sq, o);
    }
    if ((tid & 31) == 0) { redS[tid >> 5] = s; redQ[tid >> 5] = sq; }
    __syncthreads();
    if (tid < 32) {
        float a = (tid < 8) ? redS[tid] : 0.f;
        float b = (tid < 8) ? redQ[tid] : 0.f;
        #pragma unroll
        for (int o = 4; o > 0; o >>= 1) {
            a += __shfl_down_sync(0xffffffffu, a, o);
            b += __shfl_down_sync(0xffffffffu, b, o);
        }
        if (tid == 0) { redS[0] = a; redQ[0] = b; }
    }
    __syncthreads();

    float mu = redS[0] * (1.0f / D_);
    float var = redQ[0] * (1.0f / D_) - mu * mu;
    float rstd = rsqrtf(var + 1e-6f);

    float* o = out + (size_t)row * D_;
    o[tid]       = (v0 - mu) * rstd * gamma[tid] + beta[tid];
    o[tid + 256] = (v1 - mu) * rstd * gamma[tid + 256] + beta[tid + 256];
}

// ---------------------------------------------------------------------------
// Launcher — launch index 3 = gemm0 (the ncu-profiled slot)
// ---------------------------------------------------------------------------
extern "C" void kernel_launch(void* const* d_in, const int* in_sizes, int n_in,
                              void* d_out, int out_size) {
    const float* summ   = (const float*)d_in[0];
    const float* dec    = (const float*)d_in[1];
    const float* W_hist = (const float*)d_in[2];
    const float* b_hist = (const float*)d_in[3];
    const float* W1     = (const float*)d_in[4];
    const float* W2     = (const float*)d_in[5];
    const float* W_out  = (const float*)d_in[6];
    const float* b_out  = (const float*)d_in[7];
    const float* gamma  = (const float*)d_in[8];
    const float* beta   = (const float*)d_in[9];
    float* out = (float*)d_out;

    float *bufA, *bufB, *summp, *wt;
    cudaGetSymbolAddress((void**)&bufA,  g_bufA);
    cudaGetSymbolAddress((void**)&bufB,  g_bufB);
    cudaGetSymbolAddress((void**)&summp, g_summ);
    cudaGetSymbolAddress((void**)&wt,    g_Wt);
    float* WtHist = wt;
    float* WtW2   = wt + (size_t)D_ * D_;
    float* WtOut  = wt + 2 * (size_t)D_ * D_;

    cudaFuncSetAttribute(tc_gemm<0>, cudaFuncAttributeMaxDynamicSharedMemorySize, GEMM_SMEM);
    cudaFuncSetAttribute(tc_gemm<1>, cudaFuncAttributeMaxDynamicSharedMemorySize, GEMM_SMEM);
    cudaFuncSetAttribute(tc_gemm<2>, cudaFuncAttributeMaxDynamicSharedMemorySize, GEMM_SMEM);

    // 0: chunk sums
    chunk_sum_kernel<<<B_ * NCHUNK, D_>>>(dec);
    // 1: prefix + weight transposes + summ_proj (fused)
    prep_kernel<<<808, 512>>>(summ, W1, W_hist, W2, W_out);
    // 2: causal running mean -> bufA (interleaved)
    cum_mean_kernel<<<B_ * NCHUNK, D_>>>(dec);

    // 3-5: GEMM chain
    dim3 ggrid(D_ / TILE_N, M_TOTAL / TILE_M);   // (8, 256)
    tc_gemm<0><<<ggrid, GM_THREADS, GEMM_SMEM>>>(bufA, WtHist, b_hist, nullptr, bufB);
    tc_gemm<1><<<ggrid, GM_THREADS, GEMM_SMEM>>>(bufB, WtW2,   summp,  nullptr, bufA);
    tc_gemm<2><<<ggrid, GM_THREADS, GEMM_SMEM>>>(bufA, WtOut,  b_out,  dec,     bufB);

    // 6: LayerNorm
    layernorm_kernel<<<M_TOTAL, 256>>>(bufB, gamma, beta, out);
}

// round 8
// speedup vs baseline: 1.6750x; 1.6750x over previous
#include <cuda_runtime.h>
#include <cuda_fp16.h>
#include <math.h>
#include <stdint.h>

// ---------------------------------------------------------------------------
// Problem constants
// ---------------------------------------------------------------------------
#define B_ 8
#define T_ 4096
#define D_ 512
#define M_TOTAL (B_ * T_)          // 32768
#define CHUNK 128
#define NCHUNK (T_ / CHUNK)        // 32
#define NSTH 8                     // k-stages (BK=64, fp16)

// ---------------------------------------------------------------------------
// Scratch
// ---------------------------------------------------------------------------
__device__ __half g_hbufA[(size_t)M_TOTAL * D_];   // 32 MB, interleaved fp16
__device__ __half g_hbufB[(size_t)M_TOTAL * D_];
__device__ float  g_fbuf[(size_t)M_TOTAL * D_];    // fp32 pre-LN buffer
__device__ float  g_partial[B_ * NCHUNK * D_];
__device__ float  g_summ[B_ * D_];
__device__ __half g_hWt[3 * (size_t)D_ * D_];      // transposed fp16 weights

// ---------------------------------------------------------------------------
// Helpers
// ---------------------------------------------------------------------------
__device__ __forceinline__ uint32_t smem_u32(const void* p) {
    uint32_t a;
    asm("{ .reg .u64 t; cvta.to.shared.u64 t, %1; cvt.u32.u64 %0, t; }"
        : "=r"(a) : "l"(p));
    return a;
}
__device__ __forceinline__ void mma_f16_16x8x16(float* d, const uint32_t* a,
                                                const uint32_t* b) {
    asm volatile(
        "mma.sync.aligned.m16n8k16.row.col.f32.f16.f16.f32 "
        "{%0,%1,%2,%3}, {%4,%5,%6,%7}, {%8,%9}, {%0,%1,%2,%3};"
        : "+f"(d[0]), "+f"(d[1]), "+f"(d[2]), "+f"(d[3])
        : "r"(a[0]), "r"(a[1]), "r"(a[2]), "r"(a[3]),
          "r"(b[0]), "r"(b[1]));
}

#define CP_ASYNC16(dst, src) \
    asm volatile("cp.async.cg.shared.global [%0], [%1], 16;" \
                 :: "r"(dst), "l"(src) : "memory")
#define CP_COMMIT() asm volatile("cp.async.commit_group;" ::: "memory")
#define CP_WAIT1()  asm volatile("cp.async.wait_group 1;" ::: "memory")
#define CP_WAIT0()  asm volatile("cp.async.wait_group 0;" ::: "memory")

// fp16 k16-fragment interleave within a 64-wide k-stage:
// lane lr owns halves j in {2lr,2lr+1,2lr+8,2lr+9} of each k16 group; two
// groups pack into one 16B chunk -> one LDS.128 per fragment row.
__device__ __forceinline__ int kpos64(int kk) {          // kk in [0,64)
    int g = kk >> 4, j = kk & 15;
    int lr = (j >> 1) & 3;
    int idx = ((j >> 3) << 1) | (j & 1);
    return (g >> 1) * 32 + lr * 8 + (g & 1) * 4 + idx;
}
__device__ __forceinline__ size_t ileave16(int m, int k) {   // offset in halves
    return ((size_t)((m >> 7) * NSTH + (k >> 6)) * 128 + (m & 127)) * 64
           + kpos64(k & 63);
}
// SMEM XOR swizzle of 16B chunks within a 128B row
__device__ __forceinline__ int swz8(int r) {
    return (((r & 1) << 2) | ((r >> 1) & 3));
}

// ---------------------------------------------------------------------------
// chunk_sum (launch 0)
// ---------------------------------------------------------------------------
__global__ void chunk_sum_kernel(const float* __restrict__ dec) {
    int bc = blockIdx.x;
    int b = bc / NCHUNK, c = bc % NCHUNK;
    int d = threadIdx.x;
    const float* p = dec + ((size_t)(b * T_ + c * CHUNK)) * D_ + d;
    float s = 0.f;
    #pragma unroll 8
    for (int t = 0; t < CHUNK; ++t) s += p[(size_t)t * D_];
    g_partial[(size_t)bc * D_ + d] = s;
}

// ---------------------------------------------------------------------------
// prep_kernel (launch 1): chunk_prefix + 3 weight transposes + summ_proj
// ---------------------------------------------------------------------------
__global__ __launch_bounds__(512)
void prep_kernel(const float* __restrict__ summ, const float* __restrict__ W1,
                 const float* __restrict__ W_hist, const float* __restrict__ W2,
                 const float* __restrict__ W_out) {
    __shared__ float sh[1056];
    int blk = blockIdx.x;
    int tid = threadIdx.x;

    if (blk < 8) {                         // ---- chunk exclusive prefix ----
        int b = blk, d = tid;
        float run = 0.f;
        for (int c = 0; c < NCHUNK; ++c) {
            size_t idx = ((size_t)(b * NCHUNK + c)) * D_ + d;
            float v = g_partial[idx];
            g_partial[idx] = run;
            run += v;
        }
    } else if (blk < 8 + 768) {            // ---- weight transpose+interleave ----
        int idx = blk - 8;
        int w = idx >> 8;
        int r = idx & 255;
        const float* W = (w == 0) ? W_hist : (w == 1) ? W2 : W_out;
        __half* Wt = g_hWt + (size_t)w * D_ * D_;
        int bx = (r & 15) * 32, by = (r >> 4) * 32;
        if (tid < 256) {
            int x = tid & 31, y = tid >> 5;
            float(*t)[33] = (float(*)[33])sh;
            #pragma unroll
            for (int i = 0; i < 32; i += 8)
                t[y + i][x] = W[(size_t)(by + y + i) * D_ + bx + x];
            __syncthreads();
            #pragma unroll
            for (int i = 0; i < 32; i += 8)
                Wt[ileave16(bx + y + i, by + x)] = __float2half_rn(t[x][y + i]);
        } else {
            __syncthreads();
        }
    } else {                               // ---- summ_proj (fp32) ----
        int sidx = blk - 776;
        int b = sidx >> 2;
        int n0 = (sidx & 3) * 128;
        float* s = sh;
        float* red = sh + 512;
        int nl = tid & 127;
        int kg = tid >> 7;
        for (int i = tid; i < D_; i += 512) s[i] = summ[b * D_ + i];
        __syncthreads();
        float acc = 0.f;
        int k0 = kg * 128;
        #pragma unroll 8
        for (int k = 0; k < 128; ++k)
            acc = fmaf(s[k0 + k], W1[(size_t)(k0 + k) * D_ + n0 + nl], acc);
        red[kg * 128 + nl] = acc;
        __syncthreads();
        if (kg == 0)
            g_summ[b * D_ + n0 + nl] =
                red[nl] + red[128 + nl] + red[256 + nl] + red[384 + nl];
    }
}

// ---------------------------------------------------------------------------
// cum_mean (launch 2) -> g_hbufA (fp16, interleaved), 4x unrolled
// ---------------------------------------------------------------------------
__global__ void cum_mean_kernel(const float* __restrict__ dec) {
    int bc = blockIdx.x;
    int b = bc / NCHUNK, c = bc % NCHUNK;
    int d = threadIdx.x;
    size_t base = ((size_t)(b * T_ + c * CHUNK)) * D_ + d;
    float run = g_partial[(size_t)bc * D_ + d];
    size_t obase = ((size_t)((b * NCHUNK + c) * NSTH + (d >> 6)) * 128) * 64
                   + kpos64(d & 63);
    for (int t = 0; t < CHUNK; t += 4) {
        float v0 = dec[base + (size_t)(t + 0) * D_];
        float v1 = dec[base + (size_t)(t + 1) * D_];
        float v2 = dec[base + (size_t)(t + 2) * D_];
        float v3 = dec[base + (size_t)(t + 3) * D_];
        int tt = c * CHUNK + t;
        run += v0;
        g_hbufA[obase + (size_t)(t + 0) * 64] = __float2half_rn(run / (float)(tt + 1));
        run += v1;
        g_hbufA[obase + (size_t)(t + 1) * 64] = __float2half_rn(run / (float)(tt + 2));
        run += v2;
        g_hbufA[obase + (size_t)(t + 2) * 64] = __float2half_rn(run / (float)(tt + 3));
        run += v3;
        g_hbufA[obase + (size_t)(t + 3) * 64] = __float2half_rn(run / (float)(tt + 4));
    }
}

// ---------------------------------------------------------------------------
// tc_gemm: mma.sync fp16 (m16n8k16), 3-stage cp.async ring, swizzled SMEM.
// Tile 128x128, BK=64 halves (128B rows), 8 warps (4m x 2n), warp 32x64.
//   MODE 0: C(il,half) = half(tanh(acc + bias[col]))
//   MODE 1: C(il,half) = half(summ_proj[b][col] - acc)
//   MODE 2: C(fp32 plain) = tanh(acc + bias[col]) + resid
// ---------------------------------------------------------------------------
#define GM_THREADS 256
#define TILE_M 128
#define TILE_N 128
#define STG 16384                          // 128 rows x 128B

#define SM_A   0
#define SM_B   (3 * STG)                   // 49152
#define GEMM_SMEM (SM_B + 3 * STG)         // 98304 = 96KB -> 2 CTAs/SM

template <int MODE>
__global__ __launch_bounds__(GM_THREADS, 2)
void tc_gemm(const __half* __restrict__ A, const __half* __restrict__ Bt,
             const float* __restrict__ vec, const float* __restrict__ resid,
             void* __restrict__ Cv) {
    extern __shared__ char smem[];
    const uint32_t sbase = smem_u32(smem);

    const int tid = threadIdx.x;
    const int wid = tid >> 5, lane = tid & 31;
    const int row0 = blockIdx.y * TILE_M;
    const int col0 = blockIdx.x * TILE_N;
    const int wm = (wid & 3) * 32;
    const int wn = (wid >> 2) * 64;
    const int lq = lane >> 2;              // 0..7
    const int lr = lane & 3;               // 0..3

    const char* Ab = (const char*)A + (size_t)blockIdx.y * NSTH * 16384;
    const char* Bb = (const char*)Bt + (size_t)blockIdx.x * NSTH * 16384;
    const int frow = tid >> 3;             // 0..31
    const int fq = tid & 7;
    const uint32_t stchunk = (uint32_t)((fq ^ swz8(frow)) << 4);

    auto issue_stage = [&](int s, int buf) {
        const char* as = Ab + (size_t)s * 16384;
        const char* bs = Bb + (size_t)s * 16384;
        uint32_t da = sbase + SM_A + buf * STG + frow * 128 + stchunk;
        uint32_t db = sbase + SM_B + buf * STG + frow * 128 + stchunk;
        const char* sa = as + (size_t)frow * 128 + fq * 16;
        const char* sb = bs + (size_t)frow * 128 + fq * 16;
        #pragma unroll
        for (int i = 0; i < 4; ++i) {
            CP_ASYNC16(da + i * 4096, sa + (size_t)i * 4096);
            CP_ASYNC16(db + i * 4096, sb + (size_t)i * 4096);
        }
    };

    const int swzl = swz8(lq);

    float acc[2][8][4];
    #pragma unroll
    for (int mt = 0; mt < 2; ++mt)
        #pragma unroll
        for (int nt = 0; nt < 8; ++nt)
            #pragma unroll
            for (int j = 0; j < 4; ++j) acc[mt][nt][j] = 0.f;

    issue_stage(0, 0); CP_COMMIT();
    issue_stage(1, 1); CP_COMMIT();

    int buf = 0;
    for (int s = 0; s < NSTH; ++s) {
        if (s == NSTH - 1) { CP_WAIT0(); } else { CP_WAIT1(); }
        __syncthreads();
        if (s + 2 < NSTH) {
            int bufn = buf + 2; if (bufn >= 3) bufn -= 3;
            issue_stage(s + 2, bufn);
            CP_COMMIT();
        }

        const char* sa = smem + SM_A + buf * STG;
        const char* sb = smem + SM_B + buf * STG;

        #pragma unroll
        for (int c = 0; c < 2; ++c) {      // 2 chunks x 2 k16-groups each
            const int co = ((c * 4 + lr) ^ swzl) << 4;
            // A fragment rows: one LDS.128 covers both k16 groups of chunk c
            uint4 qa0[2], qa1[2];          // [mt] rows r and r+8
            #pragma unroll
            for (int mt = 0; mt < 2; ++mt) {
                int r = wm + mt * 16 + lq;
                qa0[mt] = *(const uint4*)(sa + r * 128 + co);
                qa1[mt] = *(const uint4*)(sa + (r + 8) * 128 + co);
            }
            // a frags: g0 = {q0.x, q1.x, q0.y, q1.y}; g1 = {q0.z, q1.z, q0.w, q1.w}
            uint32_t ag0[2][4], ag1[2][4];
            #pragma unroll
            for (int mt = 0; mt < 2; ++mt) {
                ag0[mt][0] = qa0[mt].x; ag0[mt][1] = qa1[mt].x;
                ag0[mt][2] = qa0[mt].y; ag0[mt][3] = qa1[mt].y;
                ag1[mt][0] = qa0[mt].z; ag1[mt][1] = qa1[mt].z;
                ag1[mt][2] = qa0[mt].w; ag1[mt][3] = qa1[mt].w;
            }
            #pragma unroll
            for (int nt = 0; nt < 8; ++nt) {
                int n = wn + nt * 8 + lq;
                uint4 p = *(const uint4*)(sb + n * 128 + co);
                uint32_t bg0[2] = { p.x, p.y };
                uint32_t bg1[2] = { p.z, p.w };
                mma_f16_16x8x16(acc[0][nt], ag0[0], bg0);
                mma_f16_16x8x16(acc[1][nt], ag0[1], bg0);
                mma_f16_16x8x16(acc[0][nt], ag1[0], bg1);
                mma_f16_16x8x16(acc[1][nt], ag1[1], bg1);
            }
        }
        if (++buf == 3) buf = 0;
    }

    // ---------------- Epilogue ----------------
    const float* vbase = (MODE == 1) ? (vec + (size_t)(row0 / T_) * D_ + col0)
                                     : (vec + col0);
    if (MODE == 2) {
        float* C = (float*)Cv;
        #pragma unroll
        for (int mt = 0; mt < 2; ++mt) {
            int row = row0 + wm + mt * 16 + lq;
            #pragma unroll
            for (int nt = 0; nt < 8; ++nt) {
                int col = wn + nt * 8 + lr * 2;
                float b0 = vbase[col], b1 = vbase[col + 1];
                float c0 = acc[mt][nt][0], c1 = acc[mt][nt][1];
                float c2 = acc[mt][nt][2], c3 = acc[mt][nt][3];
                const float* r0p = resid + (size_t)row * D_ + col0 + col;
                const float* r1p = resid + (size_t)(row + 8) * D_ + col0 + col;
                float2 o0, o1;
                o0.x = tanhf(c0 + b0) + r0p[0];
                o0.y = tanhf(c1 + b1) + r0p[1];
                o1.x = tanhf(c2 + b0) + r1p[0];
                o1.y = tanhf(c3 + b1) + r1p[1];
                *(float2*)(C + (size_t)row * D_ + col0 + col) = o0;
                *(float2*)(C + (size_t)(row + 8) * D_ + col0 + col) = o1;
            }
        }
    } else {
        __half2* C2 = (__half2*)Cv;
        const size_t tilebase = (size_t)blockIdx.y * NSTH * 8192;   // halves
        #pragma unroll
        for (int mt = 0; mt < 2; ++mt) {
            int r = wm + mt * 16 + lq;
            #pragma unroll
            for (int nt = 0; nt < 8; ++nt) {
                int col = wn + nt * 8 + lr * 2;
                int k = col0 + col;
                size_t offh = tilebase + (size_t)(k >> 6) * 8192
                              + (size_t)r * 64 + kpos64(k & 63);
                float b0 = vbase[col], b1 = vbase[col + 1];
                float c0 = acc[mt][nt][0], c1 = acc[mt][nt][1];
                float c2 = acc[mt][nt][2], c3 = acc[mt][nt][3];
                float v0, v1, v2, v3;
                if (MODE == 0) {
                    v0 = tanhf(c0 + b0); v1 = tanhf(c1 + b1);
                    v2 = tanhf(c2 + b0); v3 = tanhf(c3 + b1);
                } else {
                    v0 = b0 - c0; v1 = b1 - c1;
                    v2 = b0 - c2; v3 = b1 - c3;
                }
                C2[offh >> 1]         = __floats2half2_rn(v0, v1);   // (r,   k:k+1)
                C2[(offh >> 1) + 256] = __floats2half2_rn(v2, v3);   // (r+8, k:k+1)
            }
        }
    }
}

// ---------------------------------------------------------------------------
// LayerNorm (last launch)
// ---------------------------------------------------------------------------
__global__ __launch_bounds__(256)
void layernorm_kernel(const float* __restrict__ X,
                      const float* __restrict__ gamma,
                      const float* __restrict__ beta,
                      float* __restrict__ out) {
    int row = blockIdx.x;
    const float* x = X + (size_t)row * D_;
    int tid = threadIdx.x;

    float v0 = x[tid];
    float v1 = x[tid + 256];
    float s = v0 + v1;
    float sq = v0 * v0 + v1 * v1;

    __shared__ float redS[8], redQ[8];
    #pragma unroll
    for (int o = 16; o > 0; o >>= 1) {
        s  += __shfl_down_sync(0xffffffffu, s, o);
        sq += __shfl_down_sync(0xffffffffu, sq, o);
    }
    if ((tid & 31) == 0) { redS[tid >> 5] = s; redQ[tid >> 5] = sq; }
    __syncthreads();
    if (tid < 32) {
        float a = (tid < 8) ? redS[tid] : 0.f;
        float b = (tid < 8) ? redQ[tid] : 0.f;
        #pragma unroll
        for (int o = 4; o > 0; o >>= 1) {
            a += __shfl_down_sync(0xffffffffu, a, o);
            b += __shfl_down_sync(0xffffffffu, b, o);
        }
        if (tid == 0) { redS[0] = a; redQ[0] = b; }
    }
    __syncthreads();

    float mu = redS[0] * (1.0f / D_);
    float var = redQ[0] * (1.0f / D_) - mu * mu;
    float rstd = rsqrtf(var + 1e-6f);

    float* o = out + (size_t)row * D_;
    o[tid]       = (v0 - mu) * rstd * gamma[tid] + beta[tid];
    o[tid + 256] = (v1 - mu) * rstd * gamma[tid + 256] + beta[tid + 256];
}

// ---------------------------------------------------------------------------
// Launcher — launch index 3 = gemm0 (the ncu-profiled slot)
// ---------------------------------------------------------------------------
extern "C" void kernel_launch(void* const* d_in, const int* in_sizes, int n_in,
                              void* d_out, int out_size) {
    const float* summ   = (const float*)d_in[0];
    const float* dec    = (const float*)d_in[1];
    const float* W_hist = (const float*)d_in[2];
    const float* b_hist = (const float*)d_in[3];
    const float* W1     = (const float*)d_in[4];
    const float* W2     = (const float*)d_in[5];
    const float* W_out  = (const float*)d_in[6];
    const float* b_out  = (const float*)d_in[7];
    const float* gamma  = (const float*)d_in[8];
    const float* beta   = (const float*)d_in[9];
    float* out = (float*)d_out;

    __half *hbufA, *hbufB, *hwt;
    float *fbuf, *summp;
    cudaGetSymbolAddress((void**)&hbufA, g_hbufA);
    cudaGetSymbolAddress((void**)&hbufB, g_hbufB);
    cudaGetSymbolAddress((void**)&fbuf,  g_fbuf);
    cudaGetSymbolAddress((void**)&summp, g_summ);
    cudaGetSymbolAddress((void**)&hwt,   g_hWt);
    __half* WtHist = hwt;
    __half* WtW2   = hwt + (size_t)D_ * D_;
    __half* WtOut  = hwt + 2 * (size_t)D_ * D_;

    cudaFuncSetAttribute(tc_gemm<0>, cudaFuncAttributeMaxDynamicSharedMemorySize, GEMM_SMEM);
    cudaFuncSetAttribute(tc_gemm<1>, cudaFuncAttributeMaxDynamicSharedMemorySize, GEMM_SMEM);
    cudaFuncSetAttribute(tc_gemm<2>, cudaFuncAttributeMaxDynamicSharedMemorySize, GEMM_SMEM);

    // 0: chunk sums
    chunk_sum_kernel<<<B_ * NCHUNK, D_>>>(dec);
    // 1: prefix + weight transposes + summ_proj (fused)
    prep_kernel<<<808, 512>>>(summ, W1, W_hist, W2, W_out);
    // 2: causal running mean -> hbufA (fp16, interleaved)
    cum_mean_kernel<<<B_ * NCHUNK, D_>>>(dec);

    // 3-5: GEMM chain (fp16 tensor cores)
    dim3 ggrid(D_ / TILE_N, M_TOTAL / TILE_M);   // (4, 256)
    tc_gemm<0><<<ggrid, GM_THREADS, GEMM_SMEM>>>(hbufA, WtHist, b_hist, nullptr, hbufB);
    tc_gemm<1><<<ggrid, GM_THREADS, GEMM_SMEM>>>(hbufB, WtW2,   summp,  nullptr, hbufA);
    tc_gemm<2><<<ggrid, GM_THREADS, GEMM_SMEM>>>(hbufA, WtOut,  b_out,  dec,     fbuf);

    // 6: LayerNorm
    layernorm_kernel<<<M_TOTAL, 256>>>(fbuf, gamma, beta, out);
}

// round 9
// speedup vs baseline: 1.7205x; 1.0271x over previous
#include <cuda_runtime.h>
#include <cuda_fp16.h>
#include <math.h>
#include <stdint.h>

// ---------------------------------------------------------------------------
// Problem constants
// ---------------------------------------------------------------------------
#define B_ 8
#define T_ 4096
#define D_ 512
#define M_TOTAL (B_ * T_)          // 32768
#define CHUNK 128
#define NCHUNK (T_ / CHUNK)        // 32
#define NSTH 8                     // k-stages (BK=64, fp16)

// ---------------------------------------------------------------------------
// Scratch
// ---------------------------------------------------------------------------
__device__ __half g_hbufA[(size_t)M_TOTAL * D_];   // 32 MB, interleaved fp16
__device__ __half g_hbufB[(size_t)M_TOTAL * D_];
__device__ float  g_fbuf[(size_t)M_TOTAL * D_];    // fp32 pre-LN buffer
__device__ float  g_partial[B_ * NCHUNK * D_];
__device__ float  g_summ[B_ * D_];
__device__ __half g_hWt[3 * (size_t)D_ * D_];      // transposed fp16 weights

// ---------------------------------------------------------------------------
// Helpers
// ---------------------------------------------------------------------------
__device__ __forceinline__ uint32_t smem_u32(const void* p) {
    uint32_t a;
    asm("{ .reg .u64 t; cvta.to.shared.u64 t, %1; cvt.u32.u64 %0, t; }"
        : "=r"(a) : "l"(p));
    return a;
}
__device__ __forceinline__ void mma_f16_16x8x16(float* d, const uint32_t* a,
                                                const uint32_t* b) {
    asm volatile(
        "mma.sync.aligned.m16n8k16.row.col.f32.f16.f16.f32 "
        "{%0,%1,%2,%3}, {%4,%5,%6,%7}, {%8,%9}, {%0,%1,%2,%3};"
        : "+f"(d[0]), "+f"(d[1]), "+f"(d[2]), "+f"(d[3])
        : "r"(a[0]), "r"(a[1]), "r"(a[2]), "r"(a[3]),
          "r"(b[0]), "r"(b[1]));
}

#define CP_ASYNC16(dst, src) \
    asm volatile("cp.async.cg.shared.global [%0], [%1], 16;" \
                 :: "r"(dst), "l"(src) : "memory")
#define CP_COMMIT() asm volatile("cp.async.commit_group;" ::: "memory")
#define CP_WAIT1()  asm volatile("cp.async.wait_group 1;" ::: "memory")
#define CP_WAIT0()  asm volatile("cp.async.wait_group 0;" ::: "memory")

// fp16 k16-fragment interleave within a 64-wide k-stage:
// lane lr owns halves j in {2lr,2lr+1,2lr+8,2lr+9} of each k16 group; two
// groups pack into one 16B chunk -> one LDS.128 per fragment row.
__device__ __forceinline__ int kpos64(int kk) {          // kk in [0,64)
    int g = kk >> 4, j = kk & 15;
    int lr = (j >> 1) & 3;
    int idx = ((j >> 3) << 1) | (j & 1);
    return (g >> 1) * 32 + lr * 8 + (g & 1) * 4 + idx;
}
__device__ __forceinline__ size_t ileave16(int m, int k) {   // offset in halves
    return ((size_t)((m >> 7) * NSTH + (k >> 6)) * 128 + (m & 127)) * 64
           + kpos64(k & 63);
}
// SMEM XOR swizzle of 16B chunks within a 128B row
__device__ __forceinline__ int swz8(int r) {
    return (((r & 1) << 2) | ((r >> 1) & 3));
}

// ---------------------------------------------------------------------------
// chunk_sum (launch 0)
// ---------------------------------------------------------------------------
__global__ void chunk_sum_kernel(const float* __restrict__ dec) {
    int bc = blockIdx.x;
    int b = bc / NCHUNK, c = bc % NCHUNK;
    int d = threadIdx.x;
    const float* p = dec + ((size_t)(b * T_ + c * CHUNK)) * D_ + d;
    float s = 0.f;
    #pragma unroll 8
    for (int t = 0; t < CHUNK; ++t) s += p[(size_t)t * D_];
    g_partial[(size_t)bc * D_ + d] = s;
}

// ---------------------------------------------------------------------------
// prep_kernel (launch 1): chunk_prefix + 3 weight transposes + summ_proj
// ---------------------------------------------------------------------------
__global__ __launch_bounds__(512)
void prep_kernel(const float* __restrict__ summ, const float* __restrict__ W1,
                 const float* __restrict__ W_hist, const float* __restrict__ W2,
                 const float* __restrict__ W_out) {
    __shared__ float sh[1056];
    int blk = blockIdx.x;
    int tid = threadIdx.x;

    if (blk < 8) {                         // ---- chunk exclusive prefix ----
        int b = blk, d = tid;
        float run = 0.f;
        for (int c = 0; c < NCHUNK; ++c) {
            size_t idx = ((size_t)(b * NCHUNK + c)) * D_ + d;
            float v = g_partial[idx];
            g_partial[idx] = run;
            run += v;
        }
    } else if (blk < 8 + 768) {            // ---- weight transpose+interleave ----
        int idx = blk - 8;
        int w = idx >> 8;
        int r = idx & 255;
        const float* W = (w == 0) ? W_hist : (w == 1) ? W2 : W_out;
        __half* Wt = g_hWt + (size_t)w * D_ * D_;
        int bx = (r & 15) * 32, by = (r >> 4) * 32;
        if (tid < 256) {
            int x = tid & 31, y = tid >> 5;
            float(*t)[33] = (float(*)[33])sh;
            #pragma unroll
            for (int i = 0; i < 32; i += 8)
                t[y + i][x] = W[(size_t)(by + y + i) * D_ + bx + x];
            __syncthreads();
            #pragma unroll
            for (int i = 0; i < 32; i += 8)
                Wt[ileave16(bx + y + i, by + x)] = __float2half_rn(t[x][y + i]);
        } else {
            __syncthreads();
        }
    } else {                               // ---- summ_proj (fp32) ----
        int sidx = blk - 776;
        int b = sidx >> 2;
        int n0 = (sidx & 3) * 128;
        float* s = sh;
        float* red = sh + 512;
        int nl = tid & 127;
        int kg = tid >> 7;
        for (int i = tid; i < D_; i += 512) s[i] = summ[b * D_ + i];
        __syncthreads();
        float acc = 0.f;
        int k0 = kg * 128;
        #pragma unroll 8
        for (int k = 0; k < 128; ++k)
            acc = fmaf(s[k0 + k], W1[(size_t)(k0 + k) * D_ + n0 + nl], acc);
        red[kg * 128 + nl] = acc;
        __syncthreads();
        if (kg == 0)
            g_summ[b * D_ + n0 + nl] =
                red[nl] + red[128 + nl] + red[256 + nl] + red[384 + nl];
    }
}

// ---------------------------------------------------------------------------
// cum_mean (launch 2) -> g_hbufA (fp16, interleaved), 4x unrolled
// ---------------------------------------------------------------------------
__global__ void cum_mean_kernel(const float* __restrict__ dec) {
    int bc = blockIdx.x;
    int b = bc / NCHUNK, c = bc % NCHUNK;
    int d = threadIdx.x;
    size_t base = ((size_t)(b * T_ + c * CHUNK)) * D_ + d;
    float run = g_partial[(size_t)bc * D_ + d];
    size_t obase = ((size_t)((b * NCHUNK + c) * NSTH + (d >> 6)) * 128) * 64
                   + kpos64(d & 63);
    for (int t = 0; t < CHUNK; t += 4) {
        float v0 = dec[base + (size_t)(t + 0) * D_];
        float v1 = dec[base + (size_t)(t + 1) * D_];
        float v2 = dec[base + (size_t)(t + 2) * D_];
        float v3 = dec[base + (size_t)(t + 3) * D_];
        int tt = c * CHUNK + t;
        run += v0;
        g_hbufA[obase + (size_t)(t + 0) * 64] = __float2half_rn(run / (float)(tt + 1));
        run += v1;
        g_hbufA[obase + (size_t)(t + 1) * 64] = __float2half_rn(run / (float)(tt + 2));
        run += v2;
        g_hbufA[obase + (size_t)(t + 2) * 64] = __float2half_rn(run / (float)(tt + 3));
        run += v3;
        g_hbufA[obase + (size_t)(t + 3) * 64] = __float2half_rn(run / (float)(tt + 4));
    }
}

// ---------------------------------------------------------------------------
// tc_gemm: mma.sync fp16 (m16n8k16), fully-unrolled 3-stage cp.async ring,
// B-fragment software pipeline. Tile 128x128, BK=64, 8 warps, warp 32x64.
//   MODE 0: C(il,half) = half(tanh(acc + bias[col]))
//   MODE 1: C(il,half) = half(summ_proj[b][col] - acc)
//   MODE 2: C(fp32 plain) = tanh(acc + bias[col]) + resid
// ---------------------------------------------------------------------------
#define GM_THREADS 256
#define TILE_M 128
#define TILE_N 128
#define STG 16384                          // 128 rows x 128B

#define SM_A   0
#define SM_B   (3 * STG)                   // 49152
#define GEMM_SMEM (SM_B + 3 * STG)         // 98304 = 96KB -> 2 CTAs/SM

template <int MODE>
__global__ __launch_bounds__(GM_THREADS, 2)
void tc_gemm(const __half* __restrict__ A, const __half* __restrict__ Bt,
             const float* __restrict__ vec, const float* __restrict__ resid,
             void* __restrict__ Cv) {
    extern __shared__ char smem[];
    const uint32_t sbase = smem_u32(smem);

    const int tid = threadIdx.x;
    const int wid = tid >> 5, lane = tid & 31;
    const int row0 = blockIdx.y * TILE_M;
    const int col0 = blockIdx.x * TILE_N;
    const int wm = (wid & 3) * 32;
    const int wn = (wid >> 2) * 64;
    const int lq = lane >> 2;              // 0..7
    const int lr = lane & 3;               // 0..3

    const char* Ab = (const char*)A + (size_t)blockIdx.y * NSTH * 16384;
    const char* Bb = (const char*)Bt + (size_t)blockIdx.x * NSTH * 16384;
    const int frow = tid >> 3;             // 0..31
    const int fq = tid & 7;
    const uint32_t stchunk = (uint32_t)((fq ^ swz8(frow)) << 4);
    const uint32_t dA0 = sbase + SM_A + frow * 128 + stchunk;
    const uint32_t dB0 = sbase + SM_B + frow * 128 + stchunk;
    const size_t gsrc = (size_t)frow * 128 + fq * 16;

    const int swzl = swz8(lq);
    const int cc0 = (lr ^ swzl) << 4;          // chunk 0 byte offset
    const int cc1 = ((4 + lr) ^ swzl) << 4;    // chunk 1 byte offset

    // per-thread smem fragment base offsets (bytes)
    const int aoff = (wm + lq) * 128;          // + mt*2048, +1024 for r+8
    const int boff = (wn + lq) * 128;          // + nt*1024

    float acc[2][8][4];
    #pragma unroll
    for (int mt = 0; mt < 2; ++mt)
        #pragma unroll
        for (int nt = 0; nt < 8; ++nt)
            #pragma unroll
            for (int j = 0; j < 4; ++j) acc[mt][nt][j] = 0.f;

    #pragma unroll
    for (int p = 0; p < 2; ++p) {
        const char* as = Ab + (size_t)p * 16384;
        const char* bs = Bb + (size_t)p * 16384;
        #pragma unroll
        for (int i = 0; i < 4; ++i) {
            CP_ASYNC16(dA0 + p * STG + i * 4096, as + gsrc + (size_t)i * 4096);
            CP_ASYNC16(dB0 + p * STG + i * 4096, bs + gsrc + (size_t)i * 4096);
        }
        CP_COMMIT();
    }

    #pragma unroll
    for (int s = 0; s < NSTH; ++s) {
        const int buf = s % 3;
        if (s == NSTH - 1) { CP_WAIT0(); } else { CP_WAIT1(); }
        __syncthreads();
        if (s + 2 < NSTH) {
            const int bufn = (s + 2) % 3;
            const char* as = Ab + (size_t)(s + 2) * 16384;
            const char* bs = Bb + (size_t)(s + 2) * 16384;
            #pragma unroll
            for (int i = 0; i < 4; ++i) {
                CP_ASYNC16(dA0 + bufn * STG + i * 4096, as + gsrc + (size_t)i * 4096);
                CP_ASYNC16(dB0 + bufn * STG + i * 4096, bs + gsrc + (size_t)i * 4096);
            }
            CP_COMMIT();
        }

        const char* sa = smem + SM_A + buf * STG + aoff;
        const char* sb = smem + SM_B + buf * STG + boff;

        #pragma unroll
        for (int c = 0; c < 2; ++c) {
            const int co = c ? cc1 : cc0;
            // A fragments for this chunk (4 LDS.128)
            uint4 qa0[2], qa1[2];
            #pragma unroll
            for (int mt = 0; mt < 2; ++mt) {
                qa0[mt] = *(const uint4*)(sa + mt * 2048 + co);
                qa1[mt] = *(const uint4*)(sa + mt * 2048 + 1024 + co);
            }
            uint32_t ag0[2][4], ag1[2][4];
            #pragma unroll
            for (int mt = 0; mt < 2; ++mt) {
                ag0[mt][0] = qa0[mt].x; ag0[mt][1] = qa1[mt].x;
                ag0[mt][2] = qa0[mt].y; ag0[mt][3] = qa1[mt].y;
                ag1[mt][0] = qa0[mt].z; ag1[mt][1] = qa1[mt].z;
                ag1[mt][2] = qa0[mt].w; ag1[mt][3] = qa1[mt].w;
            }
            // B pipeline: prefetch nt+1 before nt's MMAs
            uint4 pb = *(const uint4*)(sb + co);
            #pragma unroll
            for (int nt = 0; nt < 8; ++nt) {
                uint4 pc = pb;
                if (nt < 7)
                    pb = *(const uint4*)(sb + (nt + 1) * 1024 + co);
                uint32_t bg0[2] = { pc.x, pc.y };
                uint32_t bg1[2] = { pc.z, pc.w };
                mma_f16_16x8x16(acc[0][nt], ag0[0], bg0);
                mma_f16_16x8x16(acc[1][nt], ag0[1], bg0);
                mma_f16_16x8x16(acc[0][nt], ag1[0], bg1);
                mma_f16_16x8x16(acc[1][nt], ag1[1], bg1);
            }
        }
    }

    // ---------------- Epilogue ----------------
    const float* vbase = (MODE == 1) ? (vec + (size_t)(row0 / T_) * D_ + col0)
                                     : (vec + col0);
    if (MODE == 2) {
        float* C = (float*)Cv;
        #pragma unroll
        for (int mt = 0; mt < 2; ++mt) {
            int row = row0 + wm + mt * 16 + lq;
            #pragma unroll
            for (int nt = 0; nt < 8; ++nt) {
                int col = wn + nt * 8 + lr * 2;
                float b0 = vbase[col], b1 = vbase[col + 1];
                float c0 = acc[mt][nt][0], c1 = acc[mt][nt][1];
                float c2 = acc[mt][nt][2], c3 = acc[mt][nt][3];
                const float* r0p = resid + (size_t)row * D_ + col0 + col;
                const float* r1p = resid + (size_t)(row + 8) * D_ + col0 + col;
                float2 o0, o1;
                o0.x = tanhf(c0 + b0) + r0p[0];
                o0.y = tanhf(c1 + b1) + r0p[1];
                o1.x = tanhf(c2 + b0) + r1p[0];
                o1.y = tanhf(c3 + b1) + r1p[1];
                *(float2*)(C + (size_t)row * D_ + col0 + col) = o0;
                *(float2*)(C + (size_t)(row + 8) * D_ + col0 + col) = o1;
            }
        }
    } else {
        __half2* C2 = (__half2*)Cv;
        const size_t tilebase = (size_t)blockIdx.y * NSTH * 8192;   // halves
        #pragma unroll
        for (int mt = 0; mt < 2; ++mt) {
            int r = wm + mt * 16 + lq;
            #pragma unroll
            for (int nt = 0; nt < 8; ++nt) {
                int col = wn + nt * 8 + lr * 2;
                int k = col0 + col;
                size_t offh = tilebase + (size_t)(k >> 6) * 8192
                              + (size_t)r * 64 + kpos64(k & 63);
                float b0 = vbase[col], b1 = vbase[col + 1];
                float c0 = acc[mt][nt][0], c1 = acc[mt][nt][1];
                float c2 = acc[mt][nt][2], c3 = acc[mt][nt][3];
                float v0, v1, v2, v3;
                if (MODE == 0) {
                    v0 = tanhf(c0 + b0); v1 = tanhf(c1 + b1);
                    v2 = tanhf(c2 + b0); v3 = tanhf(c3 + b1);
                } else {
                    v0 = b0 - c0; v1 = b1 - c1;
                    v2 = b0 - c2; v3 = b1 - c3;
                }
                C2[offh >> 1]         = __floats2half2_rn(v0, v1);   // (r,   k:k+1)
                C2[(offh >> 1) + 256] = __floats2half2_rn(v2, v3);   // (r+8, k:k+1)
            }
        }
    }
}

// ---------------------------------------------------------------------------
// LayerNorm (last launch)
// ---------------------------------------------------------------------------
__global__ __launch_bounds__(256)
void layernorm_kernel(const float* __restrict__ X,
                      const float* __restrict__ gamma,
                      const float* __restrict__ beta,
                      float* __restrict__ out) {
    int row = blockIdx.x;
    const float* x = X + (size_t)row * D_;
    int tid = threadIdx.x;

    float v0 = x[tid];
    float v1 = x[tid + 256];
    float s = v0 + v1;
    float sq = v0 * v0 + v1 * v1;

    __shared__ float redS[8], redQ[8];
    #pragma unroll
    for (int o = 16; o > 0; o >>= 1) {
        s  += __shfl_down_sync(0xffffffffu, s, o);
        sq += __shfl_down_sync(0xffffffffu, sq, o);
    }
    if ((tid & 31) == 0) { redS[tid >> 5] = s; redQ[tid >> 5] = sq; }
    __syncthreads();
    if (tid < 32) {
        float a = (tid < 8) ? redS[tid] : 0.f;
        float b = (tid < 8) ? redQ[tid] : 0.f;
        #pragma unroll
        for (int o = 4; o > 0; o >>= 1) {
            a += __shfl_down_sync(0xffffffffu, a, o);
            b += __shfl_down_sync(0xffffffffu, b, o);
        }
        if (tid == 0) { redS[0] = a; redQ[0] = b; }
    }
    __syncthreads();

    float mu = redS[0] * (1.0f / D_);
    float var = redQ[0] * (1.0f / D_) - mu * mu;
    float rstd = rsqrtf(var + 1e-6f);

    float* o = out + (size_t)row * D_;
    o[tid]       = (v0 - mu) * rstd * gamma[tid] + beta[tid];
    o[tid + 256] = (v1 - mu) * rstd * gamma[tid + 256] + beta[tid + 256];
}

// ---------------------------------------------------------------------------
// Launcher — launch index 3 = gemm0 (the ncu-profiled slot)
// ---------------------------------------------------------------------------
extern "C" void kernel_launch(void* const* d_in, const int* in_sizes, int n_in,
                              void* d_out, int out_size) {
    const float* summ   = (const float*)d_in[0];
    const float* dec    = (const float*)d_in[1];
    const float* W_hist = (const float*)d_in[2];
    const float* b_hist = (const float*)d_in[3];
    const float* W1     = (const float*)d_in[4];
    const float* W2     = (const float*)d_in[5];
    const float* W_out  = (const float*)d_in[6];
    const float* b_out  = (const float*)d_in[7];
    const float* gamma  = (const float*)d_in[8];
    const float* beta   = (const float*)d_in[9];
    float* out = (float*)d_out;

    __half *hbufA, *hbufB, *hwt;
    float *fbuf, *summp;
    cudaGetSymbolAddress((void**)&hbufA, g_hbufA);
    cudaGetSymbolAddress((void**)&hbufB, g_hbufB);
    cudaGetSymbolAddress((void**)&fbuf,  g_fbuf);
    cudaGetSymbolAddress((void**)&summp, g_summ);
    cudaGetSymbolAddress((void**)&hwt,   g_hWt);
    __half* WtHist = hwt;
    __half* WtW2   = hwt + (size_t)D_ * D_;
    __half* WtOut  = hwt + 2 * (size_t)D_ * D_;

    cudaFuncSetAttribute(tc_gemm<0>, cudaFuncAttributeMaxDynamicSharedMemorySize, GEMM_SMEM);
    cudaFuncSetAttribute(tc_gemm<1>, cudaFuncAttributeMaxDynamicSharedMemorySize, GEMM_SMEM);
    cudaFuncSetAttribute(tc_gemm<2>, cudaFuncAttributeMaxDynamicSharedMemorySize, GEMM_SMEM);

    // 0: chunk sums
    chunk_sum_kernel<<<B_ * NCHUNK, D_>>>(dec);
    // 1: prefix + weight transposes + summ_proj (fused)
    prep_kernel<<<808, 512>>>(summ, W1, W_hist, W2, W_out);
    // 2: causal running mean -> hbufA (fp16, interleaved)
    cum_mean_kernel<<<B_ * NCHUNK, D_>>>(dec);

    // 3-5: GEMM chain (fp16 tensor cores)
    dim3 ggrid(D_ / TILE_N, M_TOTAL / TILE_M);   // (4, 256)
    tc_gemm<0><<<ggrid, GM_THREADS, GEMM_SMEM>>>(hbufA, WtHist, b_hist, nullptr, hbufB);
    tc_gemm<1><<<ggrid, GM_THREADS, GEMM_SMEM>>>(hbufB, WtW2,   summp,  nullptr, hbufA);
    tc_gemm<2><<<ggrid, GM_THREADS, GEMM_SMEM>>>(hbufA, WtOut,  b_out,  dec,     fbuf);

    // 6: LayerNorm
    layernorm_kernel<<<M_TOTAL, 256>>>(fbuf, gamma, beta, out);
}